// round 17
// baseline (speedup 1.0000x reference)
#include <cuda_runtime.h>
#include <cuda_fp16.h>
#include <math.h>

// ============================================================================
// ThermoQuantizer, single fused kernel. Round 17: cp.async (LDGSTS) staging
// pipeline — in-flight loads decoupled from registers/occupancy.
//
// out = (1-p)*x + p * mean_c * f(x/mean_c)  ==  mean_c * G(xn)
// G tabulated at TN=384 nodes over [-10.5,10.5] as half2(A_j,B_j), replicated
// 32x bank-private (word j*32+lane -> bank==lane): conflict-free gather.
//
// Streaming: each warp owns a private 3-stage x 1KB smem ring. Lane l issues
// cp.async.cg 16B for exactly the bytes it will later read (no cross-lane
// deps, no barriers). wait_group 2 retires the oldest stage; LDS.128 pulls
// the pair of groups to registers; process; STG.128 .cs out. 3 stages x
// 1KB x 32 warps = 96KB/SM in flight — DRAM latency fully covered.
// ============================================================================

#define TN      384
#define THALF   10.5f
#define TSCALE  ((float)TN / (2.0f * THALF))
#define TOFF    ((float)TN * 0.5f)
#define FIXS    262144.0f                  // 2^18 fixed-point reduction scale
#define C23     8388608.0f                 // 2^23
#define BIGOFF  (TOFF - 0.5f + C23)
#define K2      (TOFF + C23)
#define IBASE   0x4B000000
#define DEPTH   3

__device__ __forceinline__ float rcp_approx(float x) {
    float r;
    asm("rcp.approx.f32 %0, %1;" : "=f"(r) : "f"(x));
    return r;
}
__device__ __forceinline__ int warp_sum_i(int x) {
    int r;
    asm("redux.sync.add.s32 %0, %1, 0xffffffff;" : "=r"(r) : "r"(x));
    return r;
}
__device__ __forceinline__ void cpasync16(void* smem_dst, const void* gsrc) {
    unsigned saddr = (unsigned)__cvta_generic_to_shared(smem_dst);
    asm volatile("cp.async.cg.shared.global [%0], [%1], 16;"
                 :: "r"(saddr), "l"(gsrc) : "memory");
}
#define CP_COMMIT() asm volatile("cp.async.commit_group;" ::: "memory")
#define CP_WAIT()   asm volatile("cp.async.wait_group %0;" :: "n"(DEPTH - 1) : "memory")

__device__ __forceinline__ void stcs4(float4* p, float4 v) {
    asm("st.global.cs.v4.f32 [%0], {%1,%2,%3,%4};"
        :: "l"(p), "f"(v.x), "f"(v.y), "f"(v.z), "f"(v.w) : "memory");
}

extern __shared__ __half2 tbl[];           // TN*32 entries, bank-private

__global__ __launch_bounds__(512, 2)
void tq_fused(const float4* __restrict__ x4, float4* __restrict__ out4,
              const float* __restrict__ cb, const float* __restrict__ pressure,
              const float* __restrict__ temp, int ngroups) {
    __shared__ float  vals[TN + 1];
    __shared__ float4 stage[16][DEPTH][64];   // per-warp 3-stage ring, 48 KB

    float p   = *pressure;
    float omp = 1.0f - p;

    // ---- Phase 1a: tabulate G(xn) = omp*xn + p*f(xn), two-pass softmax ----
    {
        float T = *temp + 1e-6f;
        float invT = 1.0f / T;

        for (int j = threadIdx.x; j < TN + 1; j += 512) {
            float xn = -THALF + (float)j * (2.0f * THALF / (float)TN);
            float mind2 = 3.4e38f;
#pragma unroll
            for (int i = 0; i < 16; i++) {
                float d = xn - __ldg(cb + i);
                mind2 = fminf(mind2, d * d);
            }
            float sw = 0.0f, sc = 0.0f;
#pragma unroll
            for (int i = 0; i < 16; i++) {
                float ci = __ldg(cb + i);
                float d  = xn - ci;
                float wgt = __expf((mind2 - d * d) * invT);
                sw += wgt;
                sc += wgt * ci;
            }
            vals[j] = omp * xn + p * (sc / sw);
        }
    }
    __syncthreads();
    // ---- Phase 1b: replicate into 32 bank-private copies ----
    for (int idx = threadIdx.x; idx < TN * 32; idx += 512) {
        int j = idx >> 5;
        tbl[idx] = __floats2half2_rn(vals[j], vals[j + 1] - vals[j]);
    }
    __syncthreads();

    int lane = threadIdx.x & 31;
    int wid  = threadIdx.x >> 5;
    int pair = blockIdx.x * 16 + wid;      // pair index: groups (2p, 2p+1)
    int npairs = ngroups >> 1;
    int W    = gridDim.x * 16;             // pairs advanced per iteration

    const __half2* mytbl = tbl + lane;

    // pair p covers float4 range [p*64, p*64+64)
    const float4* srcR = x4   + ((long)pair << 6) + lane;   // refill cursor
    float4*       dstp = out4 + ((long)pair << 6) + lane;
    const long pstep = (long)W << 6;

    // ---- pipeline prologue: fill DEPTH stages ----
#pragma unroll
    for (int s = 0; s < DEPTH; s++) {
        if (pair + s * W < npairs) {
            cpasync16(&stage[wid][s][lane],      srcR);
            cpasync16(&stage[wid][s][32 + lane], srcR + 32);
        }
        CP_COMMIT();
        srcR += pstep;
    }

    int niter = (pair < npairs) ? ((npairs - pair + W - 1) / W) : 0;
    int s = 0;
    for (int it = 0; it < niter; it++) {
        CP_WAIT();                         // oldest stage resident
        float4 v0 = stage[wid][s][lane];
        float4 v1 = stage[wid][s][32 + lane];

        // refill this slot for iteration it+DEPTH (LDS above already issued;
        // DMA data cannot land before it completes)
        if (pair + (it + DEPTH) * W < npairs) {
            cpasync16(&stage[wid][s][lane],      srcR);
            cpasync16(&stage[wid][s][32 + lane], srcR + 32);
        }
        CP_COMMIT();
        srcR += pstep;
        if (++s == DEPTH) s = 0;

        // ---- process the pair of groups ----
        float a0 = fabsf(v0.x) + fabsf(v0.y) + fabsf(v0.z) + fabsf(v0.w);
        float a1 = fabsf(v1.x) + fabsf(v1.y) + fabsf(v1.z) + fabsf(v1.w);
        int i0 = warp_sum_i(__float2int_rn(a0 * FIXS));
        int i1 = warp_sum_i(__float2int_rn(a1 * FIXS));
        float mean0 = fmaxf((float)i0 * (1.0f / (FIXS * 128.0f)), 1e-5f);
        float mean1 = fmaxf((float)i1 * (1.0f / (FIXS * 128.0f)), 1e-5f);
        float ks0 = rcp_approx(mean0) * TSCALE;
        float ks1 = rcp_approx(mean1) * TSCALE;

        float4 o0, o1;
#define LOOKUP(OUT, VIN, KS, MEAN)                                            \
        {                                                                     \
            float big = fmaf((VIN), (KS), BIGOFF);                            \
            int   jx  = __float_as_int(big) - IBASE;                          \
            float sfr = K2 - big;                                             \
            float fr  = fmaf((VIN), (KS), sfr);                               \
            float2 ab = __half22float2(mytbl[jx << 5]);                       \
            (OUT) = (MEAN) * fmaf(fr, ab.y, ab.x);                            \
        }
        LOOKUP(o0.x, v0.x, ks0, mean0)
        LOOKUP(o1.x, v1.x, ks1, mean1)
        LOOKUP(o0.y, v0.y, ks0, mean0)
        LOOKUP(o1.y, v1.y, ks1, mean1)
        LOOKUP(o0.z, v0.z, ks0, mean0)
        LOOKUP(o1.z, v1.z, ks1, mean1)
        LOOKUP(o0.w, v0.w, ks0, mean0)
        LOOKUP(o1.w, v1.w, ks1, mean1)
#undef LOOKUP

        stcs4(dstp, o0);
        stcs4(dstp + 32, o1);
        dstp += pstep;
    }
}

extern "C" void kernel_launch(void* const* d_in, const int* in_sizes, int n_in,
                              void* d_out, int out_size) {
    const float* x        = (const float*)d_in[0];
    const float* cb       = (const float*)d_in[1];
    const float* pressure = (const float*)d_in[2];
    const float* temp     = (const float*)d_in[3];

    int n = in_sizes[0];
    int ngroups = n / 128;

    int dyn_smem = TN * 32 * (int)sizeof(__half2);   // 48 KB table
    cudaFuncSetAttribute(tq_fused,
                         cudaFuncAttributeMaxDynamicSharedMemorySize, dyn_smem);

    int blocks = 148 * 2;   // persistent grid-stride, 2 blocks/SM
    tq_fused<<<blocks, 512, dyn_smem>>>((const float4*)x, (float4*)d_out,
                                        cb, pressure, temp, ngroups);
}